// round 3
// baseline (speedup 1.0000x reference)
#include <cuda_runtime.h>
#include <cuda_bf16.h>
#include <cstdint>
#include <cstddef>

#define DEVFN __device__ __forceinline__

namespace fa {

constexpr int QLEN = 16, HQ = 32, HKVn = 8, GQ = 4, DH = 128;
constexpr int PPS = 256, KLEN = 4096;
constexpr int TILE = 64, NITER = KLEN / TILE;     // 64 iters
constexpr int KP = 132, VP = 136;                 // smem pitches (floats)
constexpr float SCALE = 0.08838834764831845f;     // 1/sqrt(128)

// shared memory layout in floats
constexpr int K_OFF = 0;
constexpr int K_ST  = TILE * KP;                  // 8448
constexpr int V_OFF = 2 * K_ST;                   // 16896
constexpr int V_ST  = TILE * VP;                  // 8704
constexpr int P_OFF = V_OFF + 2 * V_ST;           // 34304
constexpr int P_W   = 16 * 36;                    // per-warp P tile (pitch 36)
constexpr int M_OFF = P_OFF + 8 * P_W;            // 38912
constexpr int L_OFF = M_OFF + 128;                // 39040
constexpr int SMEMF = L_OFF + 128;                // 39168 floats
constexpr int SMEMB = SMEMF * 4;                  // 156672 bytes

DEVFN void cp16(uint32_t s, const float* g) {
    asm volatile("cp.async.cg.shared.global [%0], [%1], 16;\n" :: "r"(s), "l"(g) : "memory");
}
DEVFN void cp_commit() { asm volatile("cp.async.commit_group;\n" ::: "memory"); }
DEVFN void cp_wait3()  { asm volatile("cp.async.wait_group 3;\n" ::: "memory"); }
DEVFN void cp_wait0()  { asm volatile("cp.async.wait_group 0;\n" ::: "memory"); }

DEVFN uint32_t cvt_tf32(float x) {               // proper rna for register-side operands
    uint32_t r;
    asm("cvt.rna.tf32.f32 %0, %1;\n" : "=r"(r) : "f"(x));
    return r;
}
// cheap round-to-nearest for SMEM-sourced operands: +half-ulp of tf32, HW truncates low 13 bits
DEVFN uint32_t rnd_tf32(float x) { return __float_as_uint(x) + 0x1000u; }

DEVFN void mma8(float* d, uint32_t a0, uint32_t a1, uint32_t a2, uint32_t a3,
                uint32_t b0, uint32_t b1) {
    asm volatile(
        "mma.sync.aligned.m16n8k8.row.col.f32.tf32.tf32.f32 "
        "{%0,%1,%2,%3},{%4,%5,%6,%7},{%8,%9},{%0,%1,%2,%3};\n"
        : "+f"(d[0]), "+f"(d[1]), "+f"(d[2]), "+f"(d[3])
        : "r"(a0), "r"(a1), "r"(a2), "r"(a3), "r"(b0), "r"(b1));
}

__global__ __launch_bounds__(256, 1) void fa_kernel(
    const float* __restrict__ q, const float* __restrict__ kc,
    const float* __restrict__ vc, const int* __restrict__ pt,
    float* __restrict__ out)
{
    extern __shared__ float sm[];
    const int b = blockIdx.y, hkv = blockIdx.x;
    const int tid = threadIdx.x;
    const int warp = tid >> 5, lane = tid & 31;
    const int r = warp & 3;          // GQA sub-head g (row group of 16 queries)
    const int c = warp >> 2;         // key half (0/1) within the 64-key tile
    const int lq = lane >> 2;        // mma groupID
    const int lk = lane & 3;         // mma threadID-in-group
    const uint32_t smb = (uint32_t)__cvta_generic_to_shared(sm);
    const int* ptb = pt + b * PPS;

    // ---- cp.async producers: 256 threads x 8 x 16B chunks per 64x128 tile ----
    auto issueK = [&](int it) {
        const int stage = it & 1;
#pragma unroll
        for (int u = 0; u < 8; u++) {
            int row = (tid >> 5) + 8 * u, cc = tid & 31;
            int t = it * TILE + row;
            int page = __ldg(ptb + (t >> 4));
            const float* g = kc + ((size_t)((page * 16 + (t & 15)) * HKVn + hkv)) * DH + cc * 4;
            cp16(smb + (uint32_t)(K_OFF + stage * K_ST + row * KP + cc * 4) * 4u, g);
        }
    };
    auto issueV = [&](int it) {
        const int stage = it & 1;
#pragma unroll
        for (int u = 0; u < 8; u++) {
            int row = (tid >> 5) + 8 * u, cc = tid & 31;
            int t = it * TILE + row;
            int page = __ldg(ptb + (t >> 4));
            const float* g = vc + ((size_t)((page * 16 + (t & 15)) * HKVn + hkv)) * DH + cc * 4;
            cp16(smb + (uint32_t)(V_OFF + stage * V_ST + row * VP + cc * 4) * 4u, g);
        }
    };

    // prologue: 4 commit groups K0,V0,K1,V1
    issueK(0); cp_commit();
    issueV(0); cp_commit();
    issueK(1); cp_commit();
    issueV(1); cp_commit();

    // ---- Q fragments (pre-scaled, rna tf32). Rows: q=lq and q=lq+8 of head hkv*4+r ----
    uint32_t qf0[32], qf1[32];
    {
        const float* q0 = q + ((size_t)(b * QLEN + lq) * HQ + (hkv * GQ + r)) * DH + lk;
        const float* q1 = q0 + (size_t)8 * HQ * DH;
#pragma unroll
        for (int kk = 0; kk < 16; kk++) {
            qf0[2 * kk]     = cvt_tf32(q0[8 * kk] * SCALE);
            qf0[2 * kk + 1] = cvt_tf32(q0[8 * kk + 4] * SCALE);
            qf1[2 * kk]     = cvt_tf32(q1[8 * kk] * SCALE);
            qf1[2 * kk + 1] = cvt_tf32(q1[8 * kk + 4] * SCALE);
        }
    }

    // O accumulators: o[nn] covers d = 8nn + 2lk + {0,1}, rows lq / lq+8
    float o[16][4];
#pragma unroll
    for (int nn = 0; nn < 16; nn++) o[nn][0] = o[nn][1] = o[nn][2] = o[nn][3] = 0.f;
    float m0 = -1e30f, m1 = -1e30f, l0 = 0.f, l1 = 0.f;
    float* Pw = sm + P_OFF + warp * P_W;

    for (int it = 0; it < NITER; ++it) {
        const int stage = it & 1;

        cp_wait3();
        __syncthreads();                       // K_it visible

        // ---- S = Q K^T : 16 rows x 32 keys per warp ----
        float s[4][4];
#pragma unroll
        for (int n = 0; n < 4; n++) s[n][0] = s[n][1] = s[n][2] = s[n][3] = 0.f;
        const float* Kst = sm + K_OFF + stage * K_ST + (32 * c) * KP;
#pragma unroll
        for (int kk = 0; kk < 16; kk++) {
            uint32_t a0 = qf0[2 * kk], a1 = qf1[2 * kk];
            uint32_t a2 = qf0[2 * kk + 1], a3 = qf1[2 * kk + 1];
#pragma unroll
            for (int n = 0; n < 4; n++) {
                const float* kp = Kst + (8 * n + lq) * KP + 8 * kk + lk;
                mma8(s[n], a0, a1, a2, a3, rnd_tf32(kp[0]), rnd_tf32(kp[4]));
            }
        }
        __syncthreads();                       // everyone done reading K slot
        if (it + 2 < NITER) issueK(it + 2);
        cp_commit();

        cp_wait3();
        __syncthreads();                       // V_it visible

        // ---- causal mask (queries sit at 4080..4095; only last tile masks) ----
        if (it == NITER - 1) {
            const int qp0 = KLEN - QLEN + lq, qp1 = qp0 + 8;
#pragma unroll
            for (int n = 0; n < 4; n++) {
                int key = it * TILE + 32 * c + 8 * n + 2 * lk;
                if (key     > qp0) s[n][0] = -1e30f;
                if (key + 1 > qp0) s[n][1] = -1e30f;
                if (key     > qp1) s[n][2] = -1e30f;
                if (key + 1 > qp1) s[n][3] = -1e30f;
            }
        }

        // ---- warp-local online softmax over this warp's 32 keys ----
        float mx0 = fmaxf(fmaxf(s[0][0], s[0][1]), fmaxf(s[1][0], s[1][1]));
        mx0 = fmaxf(mx0, fmaxf(fmaxf(s[2][0], s[2][1]), fmaxf(s[3][0], s[3][1])));
        float mx1 = fmaxf(fmaxf(s[0][2], s[0][3]), fmaxf(s[1][2], s[1][3]));
        mx1 = fmaxf(mx1, fmaxf(fmaxf(s[2][2], s[2][3]), fmaxf(s[3][2], s[3][3])));
        mx0 = fmaxf(mx0, __shfl_xor_sync(0xffffffffu, mx0, 1));
        mx0 = fmaxf(mx0, __shfl_xor_sync(0xffffffffu, mx0, 2));
        mx1 = fmaxf(mx1, __shfl_xor_sync(0xffffffffu, mx1, 1));
        mx1 = fmaxf(mx1, __shfl_xor_sync(0xffffffffu, mx1, 2));

        float m0n = fmaxf(m0, mx0), m1n = fmaxf(m1, mx1);
        float f0 = __expf(m0 - m0n), f1 = __expf(m1 - m1n);
        float sum0 = 0.f, sum1 = 0.f;
#pragma unroll
        for (int n = 0; n < 4; n++) {
            s[n][0] = __expf(s[n][0] - m0n);  s[n][1] = __expf(s[n][1] - m0n);
            s[n][2] = __expf(s[n][2] - m1n);  s[n][3] = __expf(s[n][3] - m1n);
            sum0 += s[n][0] + s[n][1];
            sum1 += s[n][2] + s[n][3];
        }
        sum0 += __shfl_xor_sync(0xffffffffu, sum0, 1);
        sum0 += __shfl_xor_sync(0xffffffffu, sum0, 2);
        sum1 += __shfl_xor_sync(0xffffffffu, sum1, 1);
        sum1 += __shfl_xor_sync(0xffffffffu, sum1, 2);
        l0 = l0 * f0 + sum0;  l1 = l1 * f1 + sum1;
        m0 = m0n;  m1 = m1n;
#pragma unroll
        for (int nn = 0; nn < 16; nn++) {
            o[nn][0] *= f0; o[nn][1] *= f0; o[nn][2] *= f1; o[nn][3] *= f1;
        }

        // ---- P: C-fragment -> SMEM -> A-fragment (warp-private tile) ----
#pragma unroll
        for (int n = 0; n < 4; n++) {
            *reinterpret_cast<float2*>(Pw + lq * 36 + 8 * n + 2 * lk)       = make_float2(s[n][0], s[n][1]);
            *reinterpret_cast<float2*>(Pw + (lq + 8) * 36 + 8 * n + 2 * lk) = make_float2(s[n][2], s[n][3]);
        }
        __syncwarp();

        // ---- O += P V ----
        const float* Vst = sm + V_OFF + stage * V_ST + (32 * c) * VP;
#pragma unroll
        for (int kk = 0; kk < 4; kk++) {
            uint32_t pa0 = rnd_tf32(Pw[lq * 36 + 8 * kk + lk]);
            uint32_t pa1 = rnd_tf32(Pw[(lq + 8) * 36 + 8 * kk + lk]);
            uint32_t pa2 = rnd_tf32(Pw[lq * 36 + 8 * kk + lk + 4]);
            uint32_t pa3 = rnd_tf32(Pw[(lq + 8) * 36 + 8 * kk + lk + 4]);
            const float* vrow = Vst + (8 * kk + lk) * VP + lq;
#pragma unroll
            for (int nn = 0; nn < 16; nn++) {
                mma8(o[nn], pa0, pa1, pa2, pa3,
                     rnd_tf32(vrow[8 * nn]), rnd_tf32(vrow[8 * nn + 4 * VP]));
            }
        }
        __syncthreads();                       // everyone done reading V slot
        if (it + 2 < NITER) issueV(it + 2);
        cp_commit();
    }

    // ---- merge the two key-half warps (c=0 owns the final write) ----
    cp_wait0();
    __syncthreads();
    if (lk == 0) {
        sm[M_OFF + warp * 16 + lq]     = m0;  sm[M_OFF + warp * 16 + lq + 8] = m1;
        sm[L_OFF + warp * 16 + lq]     = l0;  sm[L_OFF + warp * 16 + lq + 8] = l1;
    }
    if (c == 1) {
        float* Ob = sm + K_OFF + r * 16 * KP;   // reuse K buffers
#pragma unroll
        for (int nn = 0; nn < 16; nn++) {
            *reinterpret_cast<float2*>(Ob + lq * KP + 8 * nn + 2 * lk)       = make_float2(o[nn][0], o[nn][1]);
            *reinterpret_cast<float2*>(Ob + (lq + 8) * KP + 8 * nn + 2 * lk) = make_float2(o[nn][2], o[nn][3]);
        }
    }
    __syncthreads();
    if (c == 0) {
        const int pw = r + 4;                  // partner warp
        float mB0 = sm[M_OFF + pw * 16 + lq],     lB0 = sm[L_OFF + pw * 16 + lq];
        float mB1 = sm[M_OFF + pw * 16 + lq + 8], lB1 = sm[L_OFF + pw * 16 + lq + 8];
        float mS0 = fmaxf(m0, mB0), mS1 = fmaxf(m1, mB1);
        float a0s = __expf(m0 - mS0), b0s = __expf(mB0 - mS0);
        float a1s = __expf(m1 - mS1), b1s = __expf(mB1 - mS1);
        float inv0 = 1.f / (a0s * l0 + b0s * lB0);
        float inv1 = 1.f / (a1s * l1 + b1s * lB1);
        const float* Ob = sm + K_OFF + r * 16 * KP;
        float* op0 = out + ((size_t)(b * QLEN + lq) * HQ + (hkv * GQ + r)) * DH;
        float* op1 = op0 + (size_t)8 * HQ * DH;
#pragma unroll
        for (int nn = 0; nn < 16; nn++) {
            int d = 8 * nn + 2 * lk;
            float pB0 = Ob[lq * KP + d],       pB1 = Ob[lq * KP + d + 1];
            float pB2 = Ob[(lq + 8) * KP + d], pB3 = Ob[(lq + 8) * KP + d + 1];
            *reinterpret_cast<float2*>(op0 + d) = make_float2(
                (a0s * o[nn][0] + b0s * pB0) * inv0, (a0s * o[nn][1] + b0s * pB1) * inv0);
            *reinterpret_cast<float2*>(op1 + d) = make_float2(
                (a1s * o[nn][2] + b1s * pB2) * inv1, (a1s * o[nn][3] + b1s * pB3) * inv1);
        }
    }
}

} // namespace fa

extern "C" void kernel_launch(void* const* d_in, const int* in_sizes, int n_in,
                              void* d_out, int out_size) {
    const float* q  = (const float*)d_in[0];
    const float* kc = (const float*)d_in[1];
    const float* vc = (const float*)d_in[2];
    const int*   pt = (const int*)d_in[3];
    float* out = (float*)d_out;

    cudaFuncSetAttribute(fa::fa_kernel, cudaFuncAttributeMaxDynamicSharedMemorySize, fa::SMEMB);
    dim3 grid(fa::HKVn, 32);   // (hkv, batch)
    fa::fa_kernel<<<grid, 256, fa::SMEMB>>>(q, kc, vc, pt, out);
}

// round 7
// speedup vs baseline: 1.0059x; 1.0059x over previous
#include <cuda_runtime.h>
#include <cuda_bf16.h>
#include <cstdint>
#include <cstddef>

#define DEVFN __device__ __forceinline__

namespace fa {

constexpr int QLEN = 16, HQ = 32, HKVn = 8, GQ = 4, DH = 128;
constexpr int PPS = 256, KLEN = 4096;
constexpr int TILE = 32, NITER = KLEN / TILE;      // 128 iters, 2 pages per tile
constexpr int KP = 132, VP = 136;                  // smem pitches (floats)
constexpr float SCALE_L2E = 0.12752425099279628f;  // (1/sqrt(128)) * log2(e)

// shared memory layout in floats
constexpr int K_OFF = 0;
constexpr int K_ST  = TILE * KP;                   // 4224
constexpr int V_OFF = 2 * K_ST;                    // 8448
constexpr int V_ST  = TILE * VP;                   // 4352
constexpr int P_OFF = V_OFF + 2 * V_ST;            // 17152
constexpr int P_W   = 16 * 36;                     // per-warp P tile (pitch 36)
constexpr int SMEMF = P_OFF + 4 * P_W;             // 19456 floats
constexpr int SMEMB = SMEMF * 4;                   // 77824 bytes -> 2 CTAs/SM

DEVFN void cp16(uint32_t s, const float* g) {
    asm volatile("cp.async.cg.shared.global [%0], [%1], 16;\n" :: "r"(s), "l"(g) : "memory");
}
DEVFN void cp_commit() { asm volatile("cp.async.commit_group;\n" ::: "memory"); }
DEVFN void cp_wait2()  { asm volatile("cp.async.wait_group 2;\n" ::: "memory"); }
DEVFN void cp_wait0()  { asm volatile("cp.async.wait_group 0;\n" ::: "memory"); }

DEVFN uint32_t cvt_tf32(float x) {                 // round-to-nearest tf32
    uint32_t r;
    asm("cvt.rna.tf32.f32 %0, %1;\n" : "=r"(r) : "f"(x));
    return r;
}

DEVFN float ex2(float x) {                         // MUFU.EX2, flag-independent
    float r;
    asm("ex2.approx.ftz.f32 %0, %1;\n" : "=f"(r) : "f"(x));
    return r;
}

DEVFN void mma8(float* d, uint32_t a0, uint32_t a1, uint32_t a2, uint32_t a3,
                uint32_t b0, uint32_t b1) {
    asm volatile(
        "mma.sync.aligned.m16n8k8.row.col.f32.tf32.tf32.f32 "
        "{%0,%1,%2,%3},{%4,%5,%6,%7},{%8,%9},{%0,%1,%2,%3};\n"
        : "+f"(d[0]), "+f"(d[1]), "+f"(d[2]), "+f"(d[3])
        : "r"(a0), "r"(a1), "r"(a2), "r"(a3), "r"(b0), "r"(b1));
}

__global__ __launch_bounds__(128, 2) void fa_kernel(
    const float* __restrict__ q, const float* __restrict__ kc,
    const float* __restrict__ vc, const int* __restrict__ pt,
    float* __restrict__ out)
{
    extern __shared__ float sm[];
    const int b = blockIdx.y, hkv = blockIdx.x;
    const int tid = threadIdx.x;
    const int warp = tid >> 5, lane = tid & 31;   // warp == GQA sub-head (16 q rows)
    const int lq = lane >> 2;                     // mma groupID
    const int lk = lane & 3;                      // mma threadID-in-group
    const uint32_t smb = (uint32_t)__cvta_generic_to_shared(sm);
    const int* ptb = pt + b * PPS;

    // ---- cp.async producer: 32 rows x 128 floats, 2 pages/tile ----
    const int cc = tid & 31, rw = tid >> 5;       // chunk col (16B), base row
    auto issue = [&](const float* cache, int it, int off, int pitch) {
        const int stage = it & 1;
        const int p0 = __ldg(ptb + 2 * it), p1 = __ldg(ptb + 2 * it + 1);
        const float* g0 = cache + (size_t)p0 * 16384 + hkv * DH + cc * 4 + rw * 1024;
        const float* g1 = cache + (size_t)p1 * 16384 + hkv * DH + cc * 4 + rw * 1024;
        const uint32_t dst = smb + (uint32_t)(off + stage * (pitch * TILE) + rw * pitch + cc * 4) * 4u;
#pragma unroll
        for (int u = 0; u < 8; u++) {
            const float* g = (u < 4) ? g0 + u * 4096 : g1 + (u - 4) * 4096;
            cp16(dst + (uint32_t)(4 * u * pitch) * 4u, g);
        }
    };

    // ---- in-place tf32 round-to-nearest of a 32x128 tile (vectorized) ----
    auto round_tile = [&](int off, int pitch, int stage) {
        float* base = sm + off + stage * (pitch * TILE);
#pragma unroll
        for (int u = 0; u < 8; u++) {
            int i = tid + 128 * u;                // 1024 float4 chunks
            float4* p = reinterpret_cast<float4*>(base + (i >> 5) * pitch + (i & 31) * 4);
            float4 v = *p;
            uint4 w = make_uint4(__float_as_uint(v.x) + 0x1000u, __float_as_uint(v.y) + 0x1000u,
                                 __float_as_uint(v.z) + 0x1000u, __float_as_uint(v.w) + 0x1000u);
            *p = *reinterpret_cast<float4*>(&w);
        }
    };

    // prologue: commit groups K0,V0,K1,V1
    issue(kc, 0, K_OFF, KP); cp_commit();
    issue(vc, 0, V_OFF, VP); cp_commit();
    issue(kc, 1, K_OFF, KP); cp_commit();
    issue(vc, 1, V_OFF, VP); cp_commit();

    // ---- Q fragments, pre-scaled by scale*log2e, rna-tf32 ----
    uint32_t qf0[32], qf1[32];
    {
        const float* q0 = q + ((size_t)(b * QLEN + lq) * HQ + (hkv * GQ + warp)) * DH + lk;
        const float* q1 = q0 + (size_t)8 * HQ * DH;
#pragma unroll
        for (int kk = 0; kk < 16; kk++) {
            qf0[2 * kk]     = cvt_tf32(q0[8 * kk] * SCALE_L2E);
            qf0[2 * kk + 1] = cvt_tf32(q0[8 * kk + 4] * SCALE_L2E);
            qf1[2 * kk]     = cvt_tf32(q1[8 * kk] * SCALE_L2E);
            qf1[2 * kk + 1] = cvt_tf32(q1[8 * kk + 4] * SCALE_L2E);
        }
    }

    float o[16][4];
#pragma unroll
    for (int nn = 0; nn < 16; nn++) o[nn][0] = o[nn][1] = o[nn][2] = o[nn][3] = 0.f;
    float m0 = -1e30f, m1 = -1e30f, l0 = 0.f, l1 = 0.f;
    float* Pw = sm + P_OFF + warp * P_W;

    for (int it = 0; it < NITER; ++it) {
        const int stage = it & 1;

        cp_wait2();                               // K_it and V_it both landed
        __syncthreads();
        round_tile(K_OFF, KP, stage);
        round_tile(V_OFF, VP, stage);
        __syncthreads();

        // ---- S = Q K^T : 16 rows x 32 keys (whole tile) per warp ----
        float s[4][4];
#pragma unroll
        for (int n = 0; n < 4; n++) s[n][0] = s[n][1] = s[n][2] = s[n][3] = 0.f;
        const float* Kst = sm + K_OFF + stage * K_ST;
#pragma unroll
        for (int kk = 0; kk < 16; kk++) {
            uint32_t a0 = qf0[2 * kk], a1 = qf1[2 * kk];
            uint32_t a2 = qf0[2 * kk + 1], a3 = qf1[2 * kk + 1];
#pragma unroll
            for (int n = 0; n < 4; n++) {
                const float* kp = Kst + (8 * n + lq) * KP + 8 * kk + lk;
                mma8(s[n], a0, a1, a2, a3,
                     __float_as_uint(kp[0]), __float_as_uint(kp[4]));
            }
        }
        __syncthreads();                          // done reading K slot
        if (it + 2 < NITER) issue(kc, it + 2, K_OFF, KP);
        cp_commit();

        // ---- causal mask (queries at 4080..4095 -> only last tile) ----
        if (it == NITER - 1) {
            const int qp0 = KLEN - QLEN + lq, qp1 = qp0 + 8;
#pragma unroll
            for (int n = 0; n < 4; n++) {
                int key = KLEN - TILE + 8 * n + 2 * lk;
                if (key     > qp0) s[n][0] = -1e30f;
                if (key + 1 > qp0) s[n][1] = -1e30f;
                if (key     > qp1) s[n][2] = -1e30f;
                if (key + 1 > qp1) s[n][3] = -1e30f;
            }
        }

        // ---- online softmax over the 32 keys (base-2 domain) ----
        float mx0 = fmaxf(fmaxf(s[0][0], s[0][1]), fmaxf(s[1][0], s[1][1]));
        mx0 = fmaxf(mx0, fmaxf(fmaxf(s[2][0], s[2][1]), fmaxf(s[3][0], s[3][1])));
        float mx1 = fmaxf(fmaxf(s[0][2], s[0][3]), fmaxf(s[1][2], s[1][3]));
        mx1 = fmaxf(mx1, fmaxf(fmaxf(s[2][2], s[2][3]), fmaxf(s[3][2], s[3][3])));
        mx0 = fmaxf(mx0, __shfl_xor_sync(0xffffffffu, mx0, 1));
        mx0 = fmaxf(mx0, __shfl_xor_sync(0xffffffffu, mx0, 2));
        mx1 = fmaxf(mx1, __shfl_xor_sync(0xffffffffu, mx1, 1));
        mx1 = fmaxf(mx1, __shfl_xor_sync(0xffffffffu, mx1, 2));

        float m0n = fmaxf(m0, mx0), m1n = fmaxf(m1, mx1);
        bool need = (m0n > m0) | (m1n > m1);
        float f0 = ex2(m0 - m0n), f1 = ex2(m1 - m1n);
        float sum0 = 0.f, sum1 = 0.f;
#pragma unroll
        for (int n = 0; n < 4; n++) {             // exp, round-to-tf32, sum, store P
            float v0 = __uint_as_float(cvt_tf32(ex2(s[n][0] - m0n)));
            float v1 = __uint_as_float(cvt_tf32(ex2(s[n][1] - m0n)));
            float v2 = __uint_as_float(cvt_tf32(ex2(s[n][2] - m1n)));
            float v3 = __uint_as_float(cvt_tf32(ex2(s[n][3] - m1n)));
            sum0 += v0 + v1;  sum1 += v2 + v3;
            *reinterpret_cast<float2*>(Pw + lq * 36 + 8 * n + 2 * lk)       = make_float2(v0, v1);
            *reinterpret_cast<float2*>(Pw + (lq + 8) * 36 + 8 * n + 2 * lk) = make_float2(v2, v3);
        }
        sum0 += __shfl_xor_sync(0xffffffffu, sum0, 1);
        sum0 += __shfl_xor_sync(0xffffffffu, sum0, 2);
        sum1 += __shfl_xor_sync(0xffffffffu, sum1, 1);
        sum1 += __shfl_xor_sync(0xffffffffu, sum1, 2);
        l0 = l0 * f0 + sum0;  l1 = l1 * f1 + sum1;
        m0 = m0n;  m1 = m1n;
        if (__any_sync(0xffffffffu, need)) {      // skip O-rescale when max unchanged
#pragma unroll
            for (int nn = 0; nn < 16; nn++) {
                o[nn][0] *= f0; o[nn][1] *= f0; o[nn][2] *= f1; o[nn][3] *= f1;
            }
        }
        __syncwarp();                             // P visible within warp

        // ---- O += P V ----
        const float* Vst = sm + V_OFF + stage * V_ST;
#pragma unroll
        for (int kk = 0; kk < 4; kk++) {
            uint32_t pa0 = __float_as_uint(Pw[lq * 36 + 8 * kk + lk]);
            uint32_t pa1 = __float_as_uint(Pw[(lq + 8) * 36 + 8 * kk + lk]);
            uint32_t pa2 = __float_as_uint(Pw[lq * 36 + 8 * kk + lk + 4]);
            uint32_t pa3 = __float_as_uint(Pw[(lq + 8) * 36 + 8 * kk + lk + 4]);
            const float* vrow = Vst + (8 * kk + lk) * VP + lq;
#pragma unroll
            for (int nn = 0; nn < 16; nn++) {
                mma8(o[nn], pa0, pa1, pa2, pa3,
                     __float_as_uint(vrow[8 * nn]),
                     __float_as_uint(vrow[8 * nn + 4 * VP]));
            }
        }
        __syncthreads();                          // done reading V slot
        if (it + 2 < NITER) issue(vc, it + 2, V_OFF, VP);
        cp_commit();
    }

    // ---- epilogue: warp owns its 16 rows exclusively -> direct write ----
    cp_wait0();
    const float inv0 = 1.f / l0, inv1 = 1.f / l1;
    float* op0 = out + ((size_t)(b * QLEN + lq) * HQ + (hkv * GQ + warp)) * DH;
    float* op1 = op0 + (size_t)8 * HQ * DH;
#pragma unroll
    for (int nn = 0; nn < 16; nn++) {
        int d = 8 * nn + 2 * lk;
        *reinterpret_cast<float2*>(op0 + d) = make_float2(o[nn][0] * inv0, o[nn][1] * inv0);
        *reinterpret_cast<float2*>(op1 + d) = make_float2(o[nn][2] * inv1, o[nn][3] * inv1);
    }
}

} // namespace fa

extern "C" void kernel_launch(void* const* d_in, const int* in_sizes, int n_in,
                              void* d_out, int out_size) {
    const float* q  = (const float*)d_in[0];
    const float* kc = (const float*)d_in[1];
    const float* vc = (const float*)d_in[2];
    const int*   pt = (const int*)d_in[3];
    float* out = (float*)d_out;

    cudaFuncSetAttribute(fa::fa_kernel, cudaFuncAttributeMaxDynamicSharedMemorySize, fa::SMEMB);
    dim3 grid(fa::HKVn, 32);   // (hkv, batch)
    fa::fa_kernel<<<grid, 128, fa::SMEMB>>>(q, kc, vc, pt, out);
}

// round 9
// speedup vs baseline: 1.2279x; 1.2206x over previous
#include <cuda_runtime.h>
#include <cuda_bf16.h>
#include <cstdint>
#include <cstddef>

#define DEVFN __device__ __forceinline__

namespace fa {

constexpr int QLEN = 16, HQ = 32, HKVn = 8, GQ = 4, DH = 128;
constexpr int PPS = 256, KLEN = 4096;
constexpr int TILE = 32, NITER = KLEN / TILE;      // 128 iters, 2 pages/tile
constexpr int KP = 144, VP = 132, PP = 36;         // pitches (floats): KP%32=16, VP%32=4, PP%32=4
constexpr float SCALE_L2E = 0.12752425099279628f;  // (1/sqrt(128)) * log2(e)

// shared memory layout (floats)
constexpr int K_OFF = 0;
constexpr int K_ST  = TILE * KP;                   // 4608
constexpr int V_OFF = 2 * K_ST;                    // 9216
constexpr int V_ST  = TILE * VP;                   // 4224
constexpr int P_OFF = V_OFF + 2 * V_ST;            // 17664
constexpr int P_W   = 16 * PP;                     // 576 per warp
constexpr int SMEMF = P_OFF + 4 * P_W;             // 19968
constexpr int SMEMB = SMEMF * 4;                   // 79872 B -> 2 CTAs/SM

DEVFN void cp16(uint32_t s, const float* g) {
    asm volatile("cp.async.cg.shared.global [%0], [%1], 16;\n" :: "r"(s), "l"(g) : "memory");
}
DEVFN void cp_commit() { asm volatile("cp.async.commit_group;\n" ::: "memory"); }
DEVFN void cp_wait3()  { asm volatile("cp.async.wait_group 3;\n" ::: "memory"); }
DEVFN void cp_wait0()  { asm volatile("cp.async.wait_group 0;\n" ::: "memory"); }

DEVFN uint32_t cvt_tf32(float x) {                 // rna tf32
    uint32_t r;
    asm("cvt.rna.tf32.f32 %0, %1;\n" : "=r"(r) : "f"(x));
    return r;
}
DEVFN float ex2(float x) {                         // MUFU.EX2
    float r;
    asm("ex2.approx.ftz.f32 %0, %1;\n" : "=f"(r) : "f"(x));
    return r;
}
DEVFN uint32_t rnd(float x) { return __float_as_uint(x) + 0x1000u; }  // tf32 round (HW truncates)
DEVFN uint32_t fu(float x)  { return __float_as_uint(x); }

DEVFN void mma8(float* d, uint32_t a0, uint32_t a1, uint32_t a2, uint32_t a3,
                uint32_t b0, uint32_t b1) {
    asm volatile(
        "mma.sync.aligned.m16n8k8.row.col.f32.tf32.tf32.f32 "
        "{%0,%1,%2,%3},{%4,%5,%6,%7},{%8,%9},{%0,%1,%2,%3};\n"
        : "+f"(d[0]), "+f"(d[1]), "+f"(d[2]), "+f"(d[3])
        : "r"(a0), "r"(a1), "r"(a2), "r"(a3), "r"(b0), "r"(b1));
}

__global__ __launch_bounds__(128, 2) void fa_kernel(
    const float* __restrict__ q, const float* __restrict__ kc,
    const float* __restrict__ vc, const int* __restrict__ pt,
    float* __restrict__ out)
{
    extern __shared__ float sm[];
    const int b = blockIdx.y, hkv = blockIdx.x;
    const int tid = threadIdx.x;
    const int warp = tid >> 5, lane = tid & 31;   // warp = GQA sub-head (16 q rows)
    const int lq = lane >> 2;                     // mma groupID
    const int lk = lane & 3;                      // mma threadID-in-group
    const uint32_t smb = (uint32_t)__cvta_generic_to_shared(sm);
    const int* ptb = pt + b * PPS;

    // ---- cp.async producer: 32 rows x 128 floats, natural layout, 2 pages/tile ----
    const int cc = tid & 31, rw = tid >> 5;
    auto issue = [&](const float* cache, int it, int off, int pitch) {
        const int stage = it & 1;
        const int p0 = __ldg(ptb + 2 * it), p1 = __ldg(ptb + 2 * it + 1);
        const float* g0 = cache + (size_t)p0 * 16384 + hkv * DH + cc * 4 + rw * 1024;
        const float* g1 = cache + (size_t)p1 * 16384 + hkv * DH + cc * 4 + rw * 1024;
        const uint32_t dst = smb + (uint32_t)(off + stage * (pitch * TILE) + rw * pitch + cc * 4) * 4u;
#pragma unroll
        for (int u = 0; u < 8; u++) {
            const float* g = (u < 4) ? g0 + u * 4096 : g1 + (u - 4) * 4096;
            cp16(dst + (uint32_t)(4 * u * pitch) * 4u, g);
        }
    };

    // prologue: commit groups K0,V0,K1,V1
    issue(kc, 0, K_OFF, KP); cp_commit();
    issue(vc, 0, V_OFF, VP); cp_commit();
    issue(kc, 1, K_OFF, KP); cp_commit();
    issue(vc, 1, V_OFF, VP); cp_commit();

    // ---- Q fragments with k-permutation folded into register load (float4 from gmem) ----
    // For kstep pair kk2: slots use natural cols 16*kk2 + 4*lk + {0,1,2,3}
    uint32_t qf0[32], qf1[32];
    {
        const float* q0 = q + ((size_t)(b * QLEN + lq) * HQ + (hkv * GQ + warp)) * DH;
        const float* q1 = q0 + (size_t)8 * HQ * DH;
#pragma unroll
        for (int kk2 = 0; kk2 < 8; kk2++) {
            float4 a = *reinterpret_cast<const float4*>(q0 + 16 * kk2 + 4 * lk);
            float4 c = *reinterpret_cast<const float4*>(q1 + 16 * kk2 + 4 * lk);
            qf0[4 * kk2 + 0] = cvt_tf32(a.x * SCALE_L2E);
            qf0[4 * kk2 + 1] = cvt_tf32(a.y * SCALE_L2E);
            qf0[4 * kk2 + 2] = cvt_tf32(a.z * SCALE_L2E);
            qf0[4 * kk2 + 3] = cvt_tf32(a.w * SCALE_L2E);
            qf1[4 * kk2 + 0] = cvt_tf32(c.x * SCALE_L2E);
            qf1[4 * kk2 + 1] = cvt_tf32(c.y * SCALE_L2E);
            qf1[4 * kk2 + 2] = cvt_tf32(c.z * SCALE_L2E);
            qf1[4 * kk2 + 3] = cvt_tf32(c.w * SCALE_L2E);
        }
    }

    float o[16][4];
#pragma unroll
    for (int nn = 0; nn < 16; nn++) o[nn][0] = o[nn][1] = o[nn][2] = o[nn][3] = 0.f;
    float m0 = -1e30f, m1 = -1e30f, l0 = 0.f, l1 = 0.f;
    float* Pw = sm + P_OFF + warp * P_W;
    // permuted P column bases: c'(col) = (col%4)*8 + col/4
    const int pbase0 = ((2 * lk) % 4) * 8 + (2 * lk) / 4;          // e=0
    const int pbase1 = ((2 * lk + 1) % 4) * 8 + (2 * lk + 1) / 4;  // e=1

    for (int it = 0; it < NITER; ++it) {
        const int stage = it & 1;

        cp_wait3();                               // K(it) landed
        __syncthreads();

        // ---- S = Q K^T : one LDS.128 feeds two k-steps ----
        float s[4][4];
#pragma unroll
        for (int n = 0; n < 4; n++) s[n][0] = s[n][1] = s[n][2] = s[n][3] = 0.f;
        const float* Kst = sm + K_OFF + stage * K_ST;
#pragma unroll
        for (int kk2 = 0; kk2 < 8; kk2++) {
#pragma unroll
            for (int n = 0; n < 4; n++) {
                float4 kv = *reinterpret_cast<const float4*>(
                    Kst + (8 * n + lq) * KP + 16 * kk2 + 4 * lk);
                mma8(s[n], qf0[4 * kk2 + 0], qf1[4 * kk2 + 0],
                           qf0[4 * kk2 + 1], qf1[4 * kk2 + 1], rnd(kv.x), rnd(kv.y));
                mma8(s[n], qf0[4 * kk2 + 2], qf1[4 * kk2 + 2],
                           qf0[4 * kk2 + 3], qf1[4 * kk2 + 3], rnd(kv.z), rnd(kv.w));
            }
        }
        __syncthreads();                          // K slot free
        if (it + 2 < NITER) issue(kc, it + 2, K_OFF, KP);
        cp_commit();

        // ---- causal mask (only last tile; queries at 4080..4095) ----
        if (it == NITER - 1) {
            const int qp0 = KLEN - QLEN + lq, qp1 = qp0 + 8;
#pragma unroll
            for (int n = 0; n < 4; n++) {
                int key = KLEN - TILE + 8 * n + 2 * lk;
                if (key     > qp0) s[n][0] = -1e30f;
                if (key + 1 > qp0) s[n][1] = -1e30f;
                if (key     > qp1) s[n][2] = -1e30f;
                if (key + 1 > qp1) s[n][3] = -1e30f;
            }
        }

        // ---- online softmax (base-2), P to permuted SMEM ----
        float mx0 = fmaxf(fmaxf(s[0][0], s[0][1]), fmaxf(s[1][0], s[1][1]));
        mx0 = fmaxf(mx0, fmaxf(fmaxf(s[2][0], s[2][1]), fmaxf(s[3][0], s[3][1])));
        float mx1 = fmaxf(fmaxf(s[0][2], s[0][3]), fmaxf(s[1][2], s[1][3]));
        mx1 = fmaxf(mx1, fmaxf(fmaxf(s[2][2], s[2][3]), fmaxf(s[3][2], s[3][3])));
        mx0 = fmaxf(mx0, __shfl_xor_sync(0xffffffffu, mx0, 1));
        mx0 = fmaxf(mx0, __shfl_xor_sync(0xffffffffu, mx0, 2));
        mx1 = fmaxf(mx1, __shfl_xor_sync(0xffffffffu, mx1, 1));
        mx1 = fmaxf(mx1, __shfl_xor_sync(0xffffffffu, mx1, 2));

        float m0n = fmaxf(m0, mx0), m1n = fmaxf(m1, mx1);
        bool need = (m0n > m0) | (m1n > m1);
        float f0 = ex2(m0 - m0n), f1 = ex2(m1 - m1n);
        float sum0 = 0.f, sum1 = 0.f;
#pragma unroll
        for (int n = 0; n < 4; n++) {
            float v0 = __uint_as_float(cvt_tf32(ex2(s[n][0] - m0n)));
            float v1 = __uint_as_float(cvt_tf32(ex2(s[n][1] - m0n)));
            float v2 = __uint_as_float(cvt_tf32(ex2(s[n][2] - m1n)));
            float v3 = __uint_as_float(cvt_tf32(ex2(s[n][3] - m1n)));
            sum0 += v0 + v1;  sum1 += v2 + v3;
            Pw[lq * PP + pbase0 + 2 * n]       = v0;
            Pw[lq * PP + pbase1 + 2 * n]       = v1;
            Pw[(lq + 8) * PP + pbase0 + 2 * n] = v2;
            Pw[(lq + 8) * PP + pbase1 + 2 * n] = v3;
        }
        sum0 += __shfl_xor_sync(0xffffffffu, sum0, 1);
        sum0 += __shfl_xor_sync(0xffffffffu, sum0, 2);
        sum1 += __shfl_xor_sync(0xffffffffu, sum1, 1);
        sum1 += __shfl_xor_sync(0xffffffffu, sum1, 2);
        l0 = l0 * f0 + sum0;  l1 = l1 * f1 + sum1;
        m0 = m0n;  m1 = m1n;
        if (__any_sync(0xffffffffu, need)) {
#pragma unroll
            for (int nn = 0; nn < 16; nn++) {
                o[nn][0] *= f0; o[nn][1] *= f0; o[nn][2] *= f1; o[nn][3] *= f1;
            }
        }
        __syncwarp();

        // ---- P A-fragments: two LDS.128 per row cover all 4 k-steps ----
        // elem index e = 2*kk + j at permuted col 8*lk + e
        float4 pa = *reinterpret_cast<const float4*>(Pw + lq * PP + 8 * lk);
        float4 pb = *reinterpret_cast<const float4*>(Pw + lq * PP + 8 * lk + 4);
        float4 pc = *reinterpret_cast<const float4*>(Pw + (lq + 8) * PP + 8 * lk);
        float4 pd = *reinterpret_cast<const float4*>(Pw + (lq + 8) * PP + 8 * lk + 4);
        float e0[8] = {pa.x, pa.y, pa.z, pa.w, pb.x, pb.y, pb.z, pb.w};
        float e1[8] = {pc.x, pc.y, pc.z, pc.w, pd.x, pd.y, pd.z, pd.w};

        cp_wait3();                               // V(it) landed
        __syncthreads();

        // ---- O += P V  (logical n permuted: lambda=8*nn+g <-> natural col g*16+nn) ----
        const float* Vst = sm + V_OFF + stage * V_ST;
#pragma unroll
        for (int kk = 0; kk < 4; kk++) {
            uint32_t a0 = fu(e0[2 * kk]),     a1 = fu(e1[2 * kk]);
            uint32_t a2 = fu(e0[2 * kk + 1]), a3 = fu(e1[2 * kk + 1]);
            const float* v0p = Vst + (8 * kk + lk) * VP + lq * 16;
            const float* v1p = v0p + 4 * VP;
#pragma unroll
            for (int ng = 0; ng < 4; ng++) {
                float4 vb0 = *reinterpret_cast<const float4*>(v0p + 4 * ng);
                float4 vb1 = *reinterpret_cast<const float4*>(v1p + 4 * ng);
                mma8(o[4 * ng + 0], a0, a1, a2, a3, rnd(vb0.x), rnd(vb1.x));
                mma8(o[4 * ng + 1], a0, a1, a2, a3, rnd(vb0.y), rnd(vb1.y));
                mma8(o[4 * ng + 2], a0, a1, a2, a3, rnd(vb0.z), rnd(vb1.z));
                mma8(o[4 * ng + 3], a0, a1, a2, a3, rnd(vb0.w), rnd(vb1.w));
            }
        }
        __syncthreads();                          // V slot free
        if (it + 2 < NITER) issue(vc, it + 2, V_OFF, VP);
        cp_commit();
    }

    // ---- epilogue: un-permute n (natural col = (2lk+e)*16 + nn), float4 stores ----
    cp_wait0();
    const float inv0 = 1.f / l0, inv1 = 1.f / l1;
    float* op0 = out + ((size_t)(b * QLEN + lq) * HQ + (hkv * GQ + warp)) * DH;
    float* op1 = op0 + (size_t)8 * HQ * DH;
#pragma unroll
    for (int m = 0; m < 4; m++) {
        float4 w0 = make_float4(o[4*m+0][0]*inv0, o[4*m+1][0]*inv0, o[4*m+2][0]*inv0, o[4*m+3][0]*inv0);
        float4 w1 = make_float4(o[4*m+0][1]*inv0, o[4*m+1][1]*inv0, o[4*m+2][1]*inv0, o[4*m+3][1]*inv0);
        float4 w2 = make_float4(o[4*m+0][2]*inv1, o[4*m+1][2]*inv1, o[4*m+2][2]*inv1, o[4*m+3][2]*inv1);
        float4 w3 = make_float4(o[4*m+0][3]*inv1, o[4*m+1][3]*inv1, o[4*m+2][3]*inv1, o[4*m+3][3]*inv1);
        *reinterpret_cast<float4*>(op0 + 32 * lk + 4 * m)      = w0;
        *reinterpret_cast<float4*>(op0 + 32 * lk + 16 + 4 * m) = w1;
        *reinterpret_cast<float4*>(op1 + 32 * lk + 4 * m)      = w2;
        *reinterpret_cast<float4*>(op1 + 32 * lk + 16 + 4 * m) = w3;
    }
}

} // namespace fa

extern "C" void kernel_launch(void* const* d_in, const int* in_sizes, int n_in,
                              void* d_out, int out_size) {
    const float* q  = (const float*)d_in[0];
    const float* kc = (const float*)d_in[1];
    const float* vc = (const float*)d_in[2];
    const int*   pt = (const int*)d_in[3];
    float* out = (float*)d_out;

    cudaFuncSetAttribute(fa::fa_kernel, cudaFuncAttributeMaxDynamicSharedMemorySize, fa::SMEMB);
    dim3 grid(fa::HKVn, 32);   // (hkv, batch)
    fa::fa_kernel<<<grid, 128, fa::SMEMB>>>(q, kc, vc, pt, out);
}